// round 16
// baseline (speedup 1.0000x reference)
#include <cuda_runtime.h>
#include <cuda_fp16.h>
#include <cstdint>

#define N_TOK    65536
#define KCODES   8192
#define ZQ_ELEMS 4194304
#define NT       256
#define NCH      128         // chunks of 64 codes
#define NSC      64          // superchunks of 128 codes (2 chunks / sync)
#define ACC_TH   0.4096f
#define FLT_BIG  3.402823e38f

// ---- smem layout (bytes) ----
#define SOFF_Z   0           // 32768 : z tile [d64][m128] fp32
#define SOFF_B   32768       // 33792 : B fp16 frags+enorm [buf2][2 chunks][8448]
#define SOFF_ZN  66560       // 128*4
#define SOFF_IDX 67072       // 128*4
#define SMEM_SZ  67584
#define CHUNK_B  8448        // 8192 frag bytes + 256 enorm bytes
#define SC_B     16896       // 2 chunks

__device__ __align__(16) char g_B16[NCH * CHUNK_B];   // pre-baked fp16 frag image
__device__ float              g_enorm[KCODES];
__device__ float              g_loss;
__device__ unsigned int       g_done;

__device__ __forceinline__ uint32_t pack2h(float lo, float hi){
    uint32_t r; asm("cvt.rn.f16x2.f32 %0, %1, %2;" : "=r"(r) : "f"(hi), "f"(lo)); return r;
}
__device__ __forceinline__ void mma_fp16(float* d, const uint32_t* a, uint32_t b0, uint32_t b1){
    asm volatile("mma.sync.aligned.m16n8k16.row.col.f32.f16.f16.f32 "
        "{%0,%1,%2,%3}, {%4,%5,%6,%7}, {%8,%9}, {%0,%1,%2,%3};"
        : "+f"(d[0]), "+f"(d[1]), "+f"(d[2]), "+f"(d[3])
        : "r"(a[0]), "r"(a[1]), "r"(a[2]), "r"(a[3]), "r"(b0), "r"(b1));
}
#define CP_ASYNC16(dst, src) asm volatile("cp.async.ca.shared.global [%0], [%1], 16;" :: "r"(dst), "l"(src))
#define CP_COMMIT()  asm volatile("cp.async.commit_group;" ::: "memory")
#define CP_WAIT0()   asm volatile("cp.async.wait_group 0;" ::: "memory")

// ---------------------------------------------------------------------------
// K1: bake fp16 frag image (B scaled 2^13) + enorm (sequential fmaf, d asc)
// ---------------------------------------------------------------------------
__global__ void vq_pre(const float* __restrict__ emb){
    int c = blockIdx.x, tid = threadIdx.x;
    uint32_t* W = (uint32_t*)(g_B16 + (size_t)c*CHUNK_B);
    #pragma unroll
    for (int j = 0; j < 4; j++){
        int f = j*256 + tid;
        int n = f >> 4, k0 = (f & 15)*4;
        float4 v = __ldg((const float4*)(emb + (size_t)(c*64 + n)*64 + k0));
        uint32_t u0 = pack2h(v.x*8192.f, v.y*8192.f);
        uint32_t u1 = pack2h(v.z*8192.f, v.w*8192.f);
        int nt = n >> 3, ks = k0 >> 4, p = (k0 >> 3) & 1;
        int Lt = (n & 7)*4 + ((k0 & 7) >> 1);
        uint32_t* dst = W + ((nt*4 + ks)*32 + Lt)*2 + p;
        dst[0] = u0; dst[2] = u1;
    }
    if (tid < 64){
        int k = c*64 + tid;
        const float4* r = (const float4*)(emb + (size_t)k*64);
        float s = 0.f;
        #pragma unroll
        for (int i = 0; i < 16; i++){
            float4 v = __ldg(&r[i]);
            s = fmaf(v.x,v.x,s); s = fmaf(v.y,v.y,s); s = fmaf(v.z,v.z,s); s = fmaf(v.w,v.w,s);
        }
        g_enorm[k] = s;
        ((float*)(g_B16 + (size_t)c*CHUNK_B + 8192))[tid] = s;
    }
    if (c == 0 && tid == 0){ g_loss = 0.f; g_done = 0u; }
}

// ---------------------------------------------------------------------------
// K2: fp16 HMMA screen, 2 chunks per barrier period (64 syncs), 3 CTAs/SM,
//     windowed exact rescore, fused output, last-CTA finalize.
// ---------------------------------------------------------------------------
__global__ __launch_bounds__(NT, 3) void vq_main(const float* __restrict__ z,
                                                 const float* __restrict__ emb,
                                                 float* __restrict__ outz,
                                                 float* __restrict__ outIdxF, int writeF){
    extern __shared__ __align__(16) char smem[];
    float*    zS    = (float*)(smem + SOFF_Z);
    float*    znS   = (float*)(smem + SOFF_ZN);
    int*      idxSm = (int*)(smem + SOFF_IDX);

    int tid = threadIdx.x, wid = tid >> 5, lane = tid & 31;
    int n0 = blockIdx.x * 128;
    const float* zb = z + (n0 >> 12) * 262144 + (n0 & 4095);

    uint32_t bS = (uint32_t)__cvta_generic_to_shared(smem + SOFF_B);
    // load one superchunk (2 chunk images, 16896 B contiguous)
    auto issueB = [&](int sc, int b){
        const char* src = g_B16 + (size_t)sc*SC_B;
        uint32_t dst = bS + b*SC_B;
        CP_ASYNC16(dst + tid*64,      src + tid*64);
        CP_ASYNC16(dst + tid*64 + 16, src + tid*64 + 16);
        CP_ASYNC16(dst + tid*64 + 32, src + tid*64 + 32);
        CP_ASYNC16(dst + tid*64 + 48, src + tid*64 + 48);
        if (tid < 32) CP_ASYNC16(dst + 16384 + tid*16, src + 16384 + tid*16);
        CP_COMMIT();
    };

    issueB(0, 0);

    for (int i = tid; i < 64*128; i += NT){
        int d = i >> 7, m = i & 127;
        zS[d*128 + m] = zb[d*4096 + m];
    }
    __syncthreads();

    if (tid < 128){
        float s = 0.f;
        #pragma unroll
        for (int d = 0; d < 64; d++){ float v = zS[d*128 + tid]; s = fmaf(v, v, s); }
        znS[tid] = s;
    }

    // A fragments (loop-invariant)
    int r0 = wid*16 + (lane >> 2);
    uint32_t Af[4][4];
    #pragma unroll
    for (int ks = 0; ks < 4; ks++){
        int k0 = ks*16 + (lane & 3)*2;
        Af[ks][0] = pack2h(zS[(k0  )*128 + r0  ], zS[(k0+1)*128 + r0  ]);
        Af[ks][1] = pack2h(zS[(k0  )*128 + r0+8], zS[(k0+1)*128 + r0+8]);
        Af[ks][2] = pack2h(zS[(k0+8)*128 + r0  ], zS[(k0+9)*128 + r0  ]);
        Af[ks][3] = pack2h(zS[(k0+8)*128 + r0+8], zS[(k0+9)*128 + r0+8]);
    }
    CP_WAIT0();
    __syncthreads();

    float zn0 = znS[r0], zn1 = znS[r0 + 8];

    float s0[3], s1[3]; int ix0[3], ix1[3];
    #pragma unroll
    for (int j = 0; j < 3; j++){ s0[j] = -FLT_BIG; s1[j] = -FLT_BIG; ix0[j] = 0; ix1[j] = 0; }
    auto ins3 = [](float (&s)[3], int (&ix)[3], float v, int kk){
        if (v > s[2]){
            if (v > s[0]){ s[2]=s[1];ix[2]=ix[1]; s[1]=s[0];ix[1]=ix[0]; s[0]=v;ix[0]=kk; }
            else if (v > s[1]){ s[2]=s[1];ix[2]=ix[1]; s[1]=v;ix[1]=kk; }
            else { s[2]=v; ix[2]=kk; }
        }
    };

    #pragma unroll 1
    for (int sc = 0; sc < NSC; sc++){
        int buf = sc & 1;
        if (sc + 1 < NSC) issueB(sc+1, buf^1);

        #pragma unroll
        for (int sub = 0; sub < 2; sub++){
            const char* cb  = smem + SOFF_B + buf*SC_B + sub*CHUNK_B;
            const float* enB = (const float*)(cb + 8192);
            const uint2* Bb  = (const uint2*)cb;
            int kk0 = (sc*2 + sub)*64;

            #pragma unroll
            for (int h = 0; h < 2; h++){
                float acc[4][4];
                #pragma unroll
                for (int j = 0; j < 4; j++){
                    int nt = h*4 + j;
                    int c0 = nt*8 + (lane & 3)*2;
                    float2 en2 = *(const float2*)&enB[c0];
                    acc[j][0] = en2.x * -4096.f; acc[j][1] = en2.y * -4096.f;
                    acc[j][2] = acc[j][0];       acc[j][3] = acc[j][1];
                }
                #pragma unroll
                for (int ks = 0; ks < 4; ks++){
                    #pragma unroll
                    for (int j = 0; j < 4; j++){
                        int nt = h*4 + j;
                        uint2 b = Bb[(nt*4 + ks)*32 + lane];
                        mma_fp16(acc[j], Af[ks], b.x, b.y);
                    }
                }
                #pragma unroll
                for (int j = 0; j < 4; j++){
                    int nt = h*4 + j;
                    int c0 = nt*8 + (lane & 3)*2;
                    int kA = kk0 + c0, kB = kA + 1;
                    if (fmaxf(acc[j][0], acc[j][1]) > s0[2]){
                        ins3(s0, ix0, acc[j][0], kA); ins3(s0, ix0, acc[j][1], kB);
                    }
                    if (fmaxf(acc[j][2], acc[j][3]) > s1[2]){
                        ins3(s1, ix1, acc[j][2], kA); ins3(s1, ix1, acc[j][3], kB);
                    }
                }
            }
        }
        CP_WAIT0();
        __syncthreads();
    }

    // ---- quad max, windowed exact rescore, local merge ----
    float q0 = s0[0], q1 = s1[0];
    #pragma unroll
    for (int off = 1; off <= 2; off <<= 1){
        q0 = fmaxf(q0, __shfl_xor_sync(0xFFFFFFFF, q0, off));
        q1 = fmaxf(q1, __shfl_xor_sync(0xFFFFFFFF, q1, off));
    }
    float thr0 = q0 - ACC_TH, thr1 = q1 - ACC_TH;

    float rb0 = FLT_BIG, rb1 = FLT_BIG; int ri0 = 0, ri1 = 0;
    auto rescore = [&](int rloc, float sv, int idx, float thr, float zn,
                       float& rb, int& ri){
        if (sv >= thr){
            const float4* ep = (const float4*)(emb + (size_t)idx*64);
            float dot = 0.f;
            #pragma unroll 4
            for (int q = 0; q < 16; q++){
                float4 ev = __ldg(&ep[q]);
                int d = q*4;
                dot = fmaf(zS[(d  )*128 + rloc], ev.x, dot);
                dot = fmaf(zS[(d+1)*128 + rloc], ev.y, dot);
                dot = fmaf(zS[(d+2)*128 + rloc], ev.z, dot);
                dot = fmaf(zS[(d+3)*128 + rloc], ev.w, dot);
            }
            float dd = fmaf(-2.f, dot, zn + __ldg(&g_enorm[idx]));  // exact (R2-validated)
            if (dd < rb || (dd == rb && idx < ri)){ rb = dd; ri = idx; }
        }
    };
    #pragma unroll
    for (int j = 0; j < 3; j++){
        rescore(r0,     s0[j], ix0[j], thr0, zn0, rb0, ri0);
        rescore(r0 + 8, s1[j], ix1[j], thr1, zn1, rb1, ri1);
    }
    #pragma unroll
    for (int off = 1; off <= 2; off <<= 1){
        float od; int oi;
        od = __shfl_xor_sync(0xFFFFFFFF, rb0, off); oi = __shfl_xor_sync(0xFFFFFFFF, ri0, off);
        if (od < rb0 || (od == rb0 && oi < ri0)){ rb0 = od; ri0 = oi; }
        od = __shfl_xor_sync(0xFFFFFFFF, rb1, off); oi = __shfl_xor_sync(0xFFFFFFFF, ri1, off);
        if (od < rb1 || (od == rb1 && oi < ri1)){ rb1 = od; ri1 = oi; }
    }
    if ((lane & 3) == 0){
        idxSm[r0]     = ri0;
        idxSm[r0 + 8] = ri1;
    }
    __syncthreads();

    // ---- fused output: indices, z_q (STE rounding), loss partial ----
    if (writeF && tid < 128) outIdxF[n0 + tid] = (float)idxSm[tid];

    float* ob = outz + (n0 >> 12)*262144 + (n0 & 4095);
    float ls = 0.f;
    for (int i = tid; i < 64*128; i += NT){
        int cc = i >> 7, m = i & 127;
        float e  = __ldg(&emb[(size_t)idxSm[m]*64 + cc]);
        float zv = zS[cc*128 + m];
        float t  = e - zv;                 // fl(zq - zc)
        ob[cc*4096 + m] = zv + t;          // fl(zc + fl(zq - zc)) — STE replicated
        ls = fmaf(t, t, ls);
    }
    __shared__ float red[NT];
    red[tid] = ls; __syncthreads();
    for (int s = 128; s > 0; s >>= 1){
        if (tid < s) red[tid] += red[tid + s];
        __syncthreads();
    }

    // ---- last CTA finalizes loss ----
    if (tid == 0){
        atomicAdd(&g_loss, red[0]);
        __threadfence();
        unsigned int t = atomicAdd(&g_done, 1u);
        if (t == gridDim.x - 1u){
            if (writeF){
                float m = g_loss * (1.f / (float)ZQ_ELEMS);
                outz[ZQ_ELEMS] = m + 0.25f * m;
            }
            g_done = 0u;
            g_loss = 0.f;
        }
    }
}

// ---------------------------------------------------------------------------
extern "C" void kernel_launch(void* const* d_in, const int* in_sizes, int n_in,
                              void* d_out, int out_size){
    const float* z   = (const float*)d_in[0];
    const float* emb = (const float*)d_in[1];
    float* out = (float*)d_out;

    int full = (out_size >= ZQ_ELEMS + 1 + N_TOK) ? 1 : 0;

    cudaFuncSetAttribute(vq_main, cudaFuncAttributeMaxDynamicSharedMemorySize, SMEM_SZ);

    vq_pre<<<NCH, 256>>>(emb);
    vq_main<<<N_TOK/128, NT, SMEM_SZ>>>(z, emb, out,
                                        full ? (out + ZQ_ELEMS + 1) : out, full);
}

// round 17
// speedup vs baseline: 1.0399x; 1.0399x over previous
#include <cuda_runtime.h>
#include <cuda_fp16.h>
#include <cstdint>

#define N_TOK    65536
#define KCODES   8192
#define ZQ_ELEMS 4194304
#define NT       256
#define NCH      128         // all 8192 codes / 64 per chunk
#define ACC_TH   0.4096f
#define FLT_BIG  3.402823e38f

// ---- smem layout (bytes) ----
#define SOFF_Z   0           // 32768 : z tile [d64][m128] fp32
#define SOFF_B   32768       // 16896 : B fp16 frags+enorm [buf2][8448]
#define SOFF_ZN  49664       // 128*4
#define SOFF_IDX 50176       // 128*4
#define SMEM_SZ  50688
#define CHUNK_B  8448        // 8192 frag bytes + 256 enorm bytes

__device__ __align__(16) char g_B16[NCH * CHUNK_B];   // pre-baked fp16 frag image
__device__ float              g_enorm[KCODES];
__device__ float              g_loss;
__device__ unsigned int       g_done;

__device__ __forceinline__ uint32_t pack2h(float lo, float hi){
    uint32_t r; asm("cvt.rn.f16x2.f32 %0, %1, %2;" : "=r"(r) : "f"(hi), "f"(lo)); return r;
}
__device__ __forceinline__ void mma_fp16(float* d, const uint32_t* a, uint32_t b0, uint32_t b1){
    asm volatile("mma.sync.aligned.m16n8k16.row.col.f32.f16.f16.f32 "
        "{%0,%1,%2,%3}, {%4,%5,%6,%7}, {%8,%9}, {%0,%1,%2,%3};"
        : "+f"(d[0]), "+f"(d[1]), "+f"(d[2]), "+f"(d[3])
        : "r"(a[0]), "r"(a[1]), "r"(a[2]), "r"(a[3]), "r"(b0), "r"(b1));
}
#define CP_ASYNC16(dst, src) asm volatile("cp.async.ca.shared.global [%0], [%1], 16;" :: "r"(dst), "l"(src))
#define CP_COMMIT()  asm volatile("cp.async.commit_group;" ::: "memory")
#define CP_WAIT0()   asm volatile("cp.async.wait_group 0;" ::: "memory")

// ---------------------------------------------------------------------------
// K1: bake fp16 frag image (B scaled 2^13) + enorm (sequential fmaf, d asc)
// ---------------------------------------------------------------------------
__global__ void vq_pre(const float* __restrict__ emb){
    int c = blockIdx.x, tid = threadIdx.x;
    uint32_t* W = (uint32_t*)(g_B16 + (size_t)c*CHUNK_B);
    #pragma unroll
    for (int j = 0; j < 4; j++){
        int f = j*256 + tid;
        int n = f >> 4, k0 = (f & 15)*4;
        float4 v = __ldg((const float4*)(emb + (size_t)(c*64 + n)*64 + k0));
        uint32_t u0 = pack2h(v.x*8192.f, v.y*8192.f);
        uint32_t u1 = pack2h(v.z*8192.f, v.w*8192.f);
        int nt = n >> 3, ks = k0 >> 4, p = (k0 >> 3) & 1;
        int Lt = (n & 7)*4 + ((k0 & 7) >> 1);
        uint32_t* dst = W + ((nt*4 + ks)*32 + Lt)*2 + p;
        dst[0] = u0; dst[2] = u1;
    }
    if (tid < 64){
        int k = c*64 + tid;
        const float4* r = (const float4*)(emb + (size_t)k*64);
        float s = 0.f;
        #pragma unroll
        for (int i = 0; i < 16; i++){
            float4 v = __ldg(&r[i]);
            s = fmaf(v.x,v.x,s); s = fmaf(v.y,v.y,s); s = fmaf(v.z,v.z,s); s = fmaf(v.w,v.w,s);
        }
        g_enorm[k] = s;
        ((float*)(g_B16 + (size_t)c*CHUNK_B + 8192))[tid] = s;
    }
    if (c == 0 && tid == 0){ g_loss = 0.f; g_done = 0u; }
}

// ---------------------------------------------------------------------------
// K2: fp16 HMMA screen (two 4-nt half-passes per chunk, 3 CTAs/SM) +
//     windowed exact rescore + fused output + last-CTA finalize.
// ---------------------------------------------------------------------------
__global__ __launch_bounds__(NT, 3) void vq_main(const float* __restrict__ z,
                                                 const float* __restrict__ emb,
                                                 float* __restrict__ outz,
                                                 float* __restrict__ outIdxF, int writeF){
    extern __shared__ __align__(16) char smem[];
    float*    zS    = (float*)(smem + SOFF_Z);
    float*    znS   = (float*)(smem + SOFF_ZN);
    int*      idxSm = (int*)(smem + SOFF_IDX);

    int tid = threadIdx.x, wid = tid >> 5, lane = tid & 31;
    int n0 = blockIdx.x * 128;
    const float* zb = z + (n0 >> 12) * 262144 + (n0 & 4095);

    uint32_t bS = (uint32_t)__cvta_generic_to_shared(smem + SOFF_B);
    auto issueB = [&](int c, int b){
        const char* src = g_B16 + (size_t)c*CHUNK_B;
        uint32_t dst = bS + b*CHUNK_B;
        CP_ASYNC16(dst + tid*32,      src + tid*32);
        CP_ASYNC16(dst + tid*32 + 16, src + tid*32 + 16);
        if (tid < 16) CP_ASYNC16(dst + 8192 + tid*16, src + 8192 + tid*16);
        CP_COMMIT();
    };

    issueB(0, 0);

    for (int i = tid; i < 64*128; i += NT){
        int d = i >> 7, m = i & 127;
        zS[d*128 + m] = zb[d*4096 + m];
    }
    __syncthreads();

    if (tid < 128){
        float s = 0.f;
        #pragma unroll
        for (int d = 0; d < 64; d++){ float v = zS[d*128 + tid]; s = fmaf(v, v, s); }
        znS[tid] = s;
    }

    // A fragments (loop-invariant)
    int r0 = wid*16 + (lane >> 2);
    uint32_t Af[4][4];
    #pragma unroll
    for (int ks = 0; ks < 4; ks++){
        int k0 = ks*16 + (lane & 3)*2;
        Af[ks][0] = pack2h(zS[(k0  )*128 + r0  ], zS[(k0+1)*128 + r0  ]);
        Af[ks][1] = pack2h(zS[(k0  )*128 + r0+8], zS[(k0+1)*128 + r0+8]);
        Af[ks][2] = pack2h(zS[(k0+8)*128 + r0  ], zS[(k0+9)*128 + r0  ]);
        Af[ks][3] = pack2h(zS[(k0+8)*128 + r0+8], zS[(k0+9)*128 + r0+8]);
    }
    CP_WAIT0();
    __syncthreads();

    float zn0 = znS[r0], zn1 = znS[r0 + 8];

    float s0[3], s1[3]; int ix0[3], ix1[3];
    #pragma unroll
    for (int j = 0; j < 3; j++){ s0[j] = -FLT_BIG; s1[j] = -FLT_BIG; ix0[j] = 0; ix1[j] = 0; }
    auto ins3 = [](float (&s)[3], int (&ix)[3], float v, int kk){
        if (v > s[2]){
            if (v > s[0]){ s[2]=s[1];ix[2]=ix[1]; s[1]=s[0];ix[1]=ix[0]; s[0]=v;ix[0]=kk; }
            else if (v > s[1]){ s[2]=s[1];ix[2]=ix[1]; s[1]=v;ix[1]=kk; }
            else { s[2]=v; ix[2]=kk; }
        }
    };

    #pragma unroll 1
    for (int c = 0; c < NCH; c++){
        int buf = c & 1;
        if (c + 1 < NCH) issueB(c+1, buf^1);

        const float* enB = (const float*)(smem + SOFF_B + buf*CHUNK_B + 8192);
        const uint2* Bw  = (const uint2*)(smem + SOFF_B + buf*CHUNK_B) + lane;  // hoisted base
        int kk0 = c*64;

        #pragma unroll
        for (int h = 0; h < 2; h++){
            float acc[4][4];
            #pragma unroll
            for (int j = 0; j < 4; j++){
                int nt = h*4 + j;
                int c0 = nt*8 + (lane & 3)*2;
                float2 en2 = *(const float2*)&enB[c0];
                acc[j][0] = en2.x * -4096.f; acc[j][1] = en2.y * -4096.f;
                acc[j][2] = acc[j][0];       acc[j][3] = acc[j][1];
            }
            #pragma unroll
            for (int ks = 0; ks < 4; ks++){
                #pragma unroll
                for (int j = 0; j < 4; j++){
                    int nt = h*4 + j;
                    uint2 b = Bw[(nt*4 + ks)*32];
                    mma_fp16(acc[j], Af[ks], b.x, b.y);
                }
            }
            #pragma unroll
            for (int j = 0; j < 4; j++){
                int nt = h*4 + j;
                int c0 = nt*8 + (lane & 3)*2;
                int kA = kk0 + c0, kB = kA + 1;
                if (fmaxf(acc[j][0], acc[j][1]) > s0[2]){
                    ins3(s0, ix0, acc[j][0], kA); ins3(s0, ix0, acc[j][1], kB);
                }
                if (fmaxf(acc[j][2], acc[j][3]) > s1[2]){
                    ins3(s1, ix1, acc[j][2], kA); ins3(s1, ix1, acc[j][3], kB);
                }
            }
        }
        CP_WAIT0();
        __syncthreads();
    }

    // ---- quad max, windowed exact rescore, local merge ----
    float q0 = s0[0], q1 = s1[0];
    #pragma unroll
    for (int off = 1; off <= 2; off <<= 1){
        q0 = fmaxf(q0, __shfl_xor_sync(0xFFFFFFFF, q0, off));
        q1 = fmaxf(q1, __shfl_xor_sync(0xFFFFFFFF, q1, off));
    }
    float thr0 = q0 - ACC_TH, thr1 = q1 - ACC_TH;

    float rb0 = FLT_BIG, rb1 = FLT_BIG; int ri0 = 0, ri1 = 0;
    auto rescore = [&](int rloc, float sv, int idx, float thr, float zn,
                       float& rb, int& ri){
        if (sv >= thr){
            const float4* ep = (const float4*)(emb + (size_t)idx*64);
            float dot = 0.f;
            #pragma unroll 4
            for (int q = 0; q < 16; q++){
                float4 ev = __ldg(&ep[q]);
                int d = q*4;
                dot = fmaf(zS[(d  )*128 + rloc], ev.x, dot);
                dot = fmaf(zS[(d+1)*128 + rloc], ev.y, dot);
                dot = fmaf(zS[(d+2)*128 + rloc], ev.z, dot);
                dot = fmaf(zS[(d+3)*128 + rloc], ev.w, dot);
            }
            float dd = fmaf(-2.f, dot, zn + __ldg(&g_enorm[idx]));  // exact (R2-validated)
            if (dd < rb || (dd == rb && idx < ri)){ rb = dd; ri = idx; }
        }
    };
    #pragma unroll
    for (int j = 0; j < 3; j++){
        rescore(r0,     s0[j], ix0[j], thr0, zn0, rb0, ri0);
        rescore(r0 + 8, s1[j], ix1[j], thr1, zn1, rb1, ri1);
    }
    #pragma unroll
    for (int off = 1; off <= 2; off <<= 1){
        float od; int oi;
        od = __shfl_xor_sync(0xFFFFFFFF, rb0, off); oi = __shfl_xor_sync(0xFFFFFFFF, ri0, off);
        if (od < rb0 || (od == rb0 && oi < ri0)){ rb0 = od; ri0 = oi; }
        od = __shfl_xor_sync(0xFFFFFFFF, rb1, off); oi = __shfl_xor_sync(0xFFFFFFFF, ri1, off);
        if (od < rb1 || (od == rb1 && oi < ri1)){ rb1 = od; ri1 = oi; }
    }
    if ((lane & 3) == 0){
        idxSm[r0]     = ri0;
        idxSm[r0 + 8] = ri1;
    }
    __syncthreads();

    // ---- fused output: indices, z_q (STE rounding), loss partial ----
    if (writeF && tid < 128) outIdxF[n0 + tid] = (float)idxSm[tid];

    float* ob = outz + (n0 >> 12)*262144 + (n0 & 4095);
    float ls = 0.f;
    for (int i = tid; i < 64*128; i += NT){
        int cc = i >> 7, m = i & 127;
        float e  = __ldg(&emb[(size_t)idxSm[m]*64 + cc]);
        float zv = zS[cc*128 + m];
        float t  = e - zv;                 // fl(zq - zc)
        ob[cc*4096 + m] = zv + t;          // fl(zc + fl(zq - zc)) — STE replicated
        ls = fmaf(t, t, ls);
    }
    __shared__ float red[NT];
    red[tid] = ls; __syncthreads();
    for (int s = 128; s > 0; s >>= 1){
        if (tid < s) red[tid] += red[tid + s];
        __syncthreads();
    }

    // ---- last CTA finalizes loss ----
    if (tid == 0){
        atomicAdd(&g_loss, red[0]);
        __threadfence();
        unsigned int t = atomicAdd(&g_done, 1u);
        if (t == gridDim.x - 1u){
            if (writeF){
                float m = g_loss * (1.f / (float)ZQ_ELEMS);
                outz[ZQ_ELEMS] = m + 0.25f * m;
            }
            g_done = 0u;
            g_loss = 0.f;
        }
    }
}

// ---------------------------------------------------------------------------
extern "C" void kernel_launch(void* const* d_in, const int* in_sizes, int n_in,
                              void* d_out, int out_size){
    const float* z   = (const float*)d_in[0];
    const float* emb = (const float*)d_in[1];
    float* out = (float*)d_out;

    int full = (out_size >= ZQ_ELEMS + 1 + N_TOK) ? 1 : 0;

    cudaFuncSetAttribute(vq_main, cudaFuncAttributeMaxDynamicSharedMemorySize, SMEM_SZ);

    vq_pre<<<NCH, 256>>>(emb);
    vq_main<<<N_TOK/128, NT, SMEM_SZ>>>(z, emb, out,
                                        full ? (out + ZQ_ELEMS + 1) : out, full);
}